// round 13
// baseline (speedup 1.0000x reference)
#include <cuda_runtime.h>

typedef unsigned long long u64;
typedef unsigned int u32;

// ---- packed f32x2 helpers (PTX-only; ptxas never auto-fuses) ----
__device__ __forceinline__ u64 pack2(float lo, float hi) {
    u64 r; asm("mov.b64 %0, {%1, %2};" : "=l"(r) : "f"(lo), "f"(hi)); return r;
}
__device__ __forceinline__ void unpack2(u64 v, float& lo, float& hi) {
    asm("mov.b64 {%0, %1}, %2;" : "=f"(lo), "=f"(hi) : "l"(v));
}
__device__ __forceinline__ u64 fma2(u64 a, u64 b, u64 c) {
    u64 d; asm("fma.rn.f32x2 %0, %1, %2, %3;" : "=l"(d) : "l"(a), "l"(b), "l"(c)); return d;
}
// one LDS.128: two consecutive u64 words
__device__ __forceinline__ void lds2(u32 addr, u64& p0, u64& p1) {
    asm volatile("ld.shared.v2.u64 {%0, %1}, [%2];" : "=l"(p0), "=l"(p1) : "r"(addr));
}
__device__ __forceinline__ u32 smem_u32(const void* p) {
    u32 a; asm("{ .reg .u64 t; cvta.to.shared.u64 t, %1; cvt.u32.u64 %0, t; }" : "=r"(a) : "l"(p));
    return a;
}

// ---- MUFU primitives ----
__device__ __forceinline__ float ex2f(float x) { float r; asm("ex2.approx.f32 %0, %1;" : "=f"(r) : "f"(x)); return r; }
__device__ __forceinline__ float rcpf(float x) { float r; asm("rcp.approx.f32 %0, %1;" : "=f"(r) : "f"(x)); return r; }
__device__ __forceinline__ float tanhf_(float x) { return fmaf(-2.0f, rcpf(1.0f + ex2f(2.8853900817779268f * x)), 1.0f); }

#define TSTEPS 512
#define WARPS_PER_CTA 4

// One warp per batch row; lane j owns hidden unit j.
// Gate-major f32x2 accumulation (4 independent 16-deep fma2 chains).
// Weights for gates i,f in 64 registers; weights for gates g,o streamed per
// step from an 8KB per-CTA SMEM table (conflict-free lane-contiguous LDS.128)
// -> regs drop below 128 -> 4 CTAs/SM (4 warps/SMSP) to hide the step latency.
// Activation scales (±log2e) pre-folded. h unduplicated, ping-pong, 1 sync/step.
__global__ void __launch_bounds__(32 * WARPS_PER_CTA, 4)
lstm_kernel(const float* __restrict__ x,
            const float* __restrict__ W_ih,
            const float* __restrict__ W_hh,
            const float* __restrict__ b_ih,
            const float* __restrict__ b_hh,
            const float* __restrict__ W_fc,
            const float* __restrict__ b_fc,
            float* __restrict__ out, int B)
{
    // wsm[j][lane] = { w_g_pair_j(lane), w_o_pair_j(lane) } : 16B per entry.
    // Warp access at fixed j: lanes read 512 contiguous bytes -> conflict-free.
    __shared__ __align__(16) u64   wsm[16 * 32 * 2];
    __shared__ __align__(16) float hbuf[2][WARPS_PER_CTA][32];
    __shared__ __align__(16) float xsm[WARPS_PER_CTA][32];

    const int wl   = threadIdx.x >> 5;
    const int lane = threadIdx.x & 31;
    const int b    = blockIdx.x * WARPS_PER_CTA + wl;

    // sigmoid(a) = rcp(1 + ex2(-log2e*a)); tanh(a) = fma(-2, rcp(1 + ex2(2*log2e*a)), 1)
    const float SG0 = -1.4426950408889634f;  // i
    const float SG1 = -1.4426950408889634f;  // f
    const float SG2 =  2.8853900817779268f;  // g (tanh)
    const float SG3 = -1.4426950408889634f;  // o

    // ---- fill shared weight table for gates g,o (each thread: 4 j-values) ----
#pragma unroll
    for (int q = 0; q < 4; q++) {
        const int j = wl * 4 + q;
        const float* rg = W_hh + (64 + lane) * 32 + 2 * j;
        const float* ro = W_hh + (96 + lane) * 32 + 2 * j;
        wsm[(j * 32 + lane) * 2 + 0] = pack2(SG2 * rg[0], SG2 * rg[1]);
        wsm[(j * 32 + lane) * 2 + 1] = pack2(SG3 * ro[0], SG3 * ro[1]);
    }

    // ---- register weights for gates i,f: 32 u64 = 64 regs ----
    u64 w0[16], w1[16];
#pragma unroll
    for (int q = 0; q < 16; q++) {
        const float* r0 = W_hh + (lane)      * 32 + 2 * q;
        const float* r1 = W_hh + (32 + lane) * 32 + 2 * q;
        w0[q] = pack2(SG0 * r0[0], SG0 * r0[1]);
        w1[q] = pack2(SG1 * r1[0], SG1 * r1[1]);
    }
    const float wih0 = SG0 * W_ih[lane],      bia0 = SG0 * (b_ih[lane]      + b_hh[lane]);
    const float wih1 = SG1 * W_ih[32 + lane], bia1 = SG1 * (b_ih[32 + lane] + b_hh[32 + lane]);
    const float wih2 = SG2 * W_ih[64 + lane], bia2 = SG2 * (b_ih[64 + lane] + b_hh[64 + lane]);
    const float wih3 = SG3 * W_ih[96 + lane], bia3 = SG3 * (b_ih[96 + lane] + b_hh[96 + lane]);

    float h = 0.0f, c = 0.0f;
    hbuf[0][wl][lane] = 0.0f;
    __syncthreads();                 // weight table + h visible
    if (b >= B) return;

    const u32 haddr0 = smem_u32(&hbuf[0][wl][0]);
    const u32 haddr1 = smem_u32(&hbuf[1][wl][0]);
    const u32 wl16   = smem_u32(&wsm[0]) + lane * 16;   // this lane's column
    const float* xsp = &xsm[wl][0];
    const float* xb  = x + (size_t)b * TSTEPS;

#define STEP(TT, RD, WRP)                                                      \
    {                                                                          \
        const float xv = xsp[(TT)];             /* broadcast LDS.32 */         \
        u64 a0 = 0ull, a1 = 0ull, a2 = 0ull, a3 = 0ull;                        \
        _Pragma("unroll")                                                      \
        for (int m = 0; m < 8; m++) {                                          \
            u64 hA, hB, g2A, g3A, g2B, g3B;                                    \
            lds2((RD) + m * 16, hA, hB);          /* h pairs 2m, 2m+1 */       \
            lds2(wl16 + (2 * m)     * 512, g2A, g3A);                          \
            lds2(wl16 + (2 * m + 1) * 512, g2B, g3B);                          \
            a0 = fma2(w0[2 * m],     hA, a0);                                  \
            a1 = fma2(w1[2 * m],     hA, a1);                                  \
            a2 = fma2(g2A,           hA, a2);                                  \
            a3 = fma2(g3A,           hA, a3);                                  \
            a0 = fma2(w0[2 * m + 1], hB, a0);                                  \
            a1 = fma2(w1[2 * m + 1], hB, a1);                                  \
            a2 = fma2(g2B,           hB, a2);                                  \
            a3 = fma2(g3B,           hB, a3);                                  \
        }                                                                      \
        float l0, u0_, l1, u1_, l2, u2_, l3, u3_;                              \
        unpack2(a0, l0, u0_);                                                  \
        unpack2(a1, l1, u1_);                                                  \
        unpack2(a2, l2, u2_);                                                  \
        unpack2(a3, l3, u3_);                                                  \
        const float s0 = fmaf(xv, wih0, bia0) + (l0 + u0_);                    \
        const float s1 = fmaf(xv, wih1, bia1) + (l1 + u1_);                    \
        const float s2 = fmaf(xv, wih2, bia2) + (l2 + u2_);                    \
        const float s3 = fmaf(xv, wih3, bia3) + (l3 + u3_);                    \
        const float ig = rcpf(1.0f + ex2f(s0));                                \
        const float fg = rcpf(1.0f + ex2f(s1));                                \
        const float gg = fmaf(-2.0f, rcpf(1.0f + ex2f(s2)), 1.0f);             \
        const float og = rcpf(1.0f + ex2f(s3));                                \
        c = fmaf(fg, c, ig * gg);                                              \
        h = og * tanhf_(c);                                                    \
        (WRP)[lane] = h;                        /* STS.32 */                   \
        __syncwarp();                                                          \
    }

#pragma unroll 1
    for (int tc = 0; tc < TSTEPS; tc += 32) {
        xsm[wl][lane] = xb[tc + lane];           // coalesced 128B per warp
        __syncwarp();

#pragma unroll 1
        for (int tt = 0; tt < 32; tt += 2) {
            STEP(tt,     haddr0, (&hbuf[1][wl][0]))   // read buf0, write buf1
            STEP(tt + 1, haddr1, (&hbuf[0][wl][0]))   // read buf1, write buf0
        }
    }
#undef STEP

    // ---- final head: out[b] = dot(h, W_fc) + b_fc ----
    float p = h * W_fc[lane];
#pragma unroll
    for (int off = 16; off; off >>= 1)
        p += __shfl_xor_sync(0xffffffffu, p, off);
    if (lane == 0) out[b] = p + b_fc[0];
}

extern "C" void kernel_launch(void* const* d_in, const int* in_sizes, int n_in,
                              void* d_out, int out_size)
{
    const float* x    = (const float*)d_in[0];
    const float* W_ih = (const float*)d_in[1];
    const float* W_hh = (const float*)d_in[2];
    const float* b_ih = (const float*)d_in[3];
    const float* b_hh = (const float*)d_in[4];
    const float* W_fc = (const float*)d_in[5];
    const float* b_fc = (const float*)d_in[6];
    float* out = (float*)d_out;

    int B = in_sizes[0] / TSTEPS;  // x is [B, 512, 1]
    int blocks = (B + WARPS_PER_CTA - 1) / WARPS_PER_CTA;
    lstm_kernel<<<blocks, 32 * WARPS_PER_CTA>>>(x, W_ih, W_hh, b_ih, b_hh, W_fc, b_fc, out, B);
}

// round 14
// speedup vs baseline: 1.2573x; 1.2573x over previous
#include <cuda_runtime.h>

typedef unsigned long long u64;
typedef unsigned int u32;

// ---- packed f32x2 helpers (PTX-only; ptxas never auto-fuses) ----
__device__ __forceinline__ u64 pack2(float lo, float hi) {
    u64 r; asm("mov.b64 %0, {%1, %2};" : "=l"(r) : "f"(lo), "f"(hi)); return r;
}
__device__ __forceinline__ void unpack2(u64 v, float& lo, float& hi) {
    asm("mov.b64 {%0, %1}, %2;" : "=f"(lo), "=f"(hi) : "l"(v));
}
__device__ __forceinline__ u64 fma2(u64 a, u64 b, u64 c) {
    u64 d; asm("fma.rn.f32x2 %0, %1, %2, %3;" : "=l"(d) : "l"(a), "l"(b), "l"(c)); return d;
}
// one LDS.128 (broadcast): 4 consecutive floats as two f32x2 pairs
__device__ __forceinline__ void lds2(u32 addr, u64& p0, u64& p1) {
    asm volatile("ld.shared.v2.u64 {%0, %1}, [%2];" : "=l"(p0), "=l"(p1) : "r"(addr));
}
__device__ __forceinline__ u32 smem_u32(const void* p) {
    u32 a; asm("{ .reg .u64 t; cvta.to.shared.u64 t, %1; cvt.u32.u64 %0, t; }" : "=r"(a) : "l"(p));
    return a;
}

// ---- MUFU primitives ----
__device__ __forceinline__ float ex2f(float x) { float r; asm("ex2.approx.f32 %0, %1;" : "=f"(r) : "f"(x)); return r; }
__device__ __forceinline__ float rcpf(float x) { float r; asm("rcp.approx.f32 %0, %1;" : "=f"(r) : "f"(x)); return r; }
__device__ __forceinline__ float tanhf_(float x) { return fmaf(-2.0f, rcpf(1.0f + ex2f(2.8853900817779268f * x)), 1.0f); }

#define TSTEPS 512
#define WARPS_PER_CTA 4
#define ROWS_PER_WARP 2

// One warp per TWO batch rows, processed ALTERNATELY (A-step then B-step) so
// row B's fma2 chain fills row A's serial MUFU tail (in-warp ILP; no reliance
// on inter-warp scheduling). Weights (gate-major f32x2 k-pairs, activation
// scales pre-folded) shared by both rows: 128 regs. h unduplicated, ping-pong
// buffers, one syncwarp per row-step.
__global__ void __launch_bounds__(32 * WARPS_PER_CTA, 3)
lstm_kernel(const float* __restrict__ x,
            const float* __restrict__ W_ih,
            const float* __restrict__ W_hh,
            const float* __restrict__ b_ih,
            const float* __restrict__ b_hh,
            const float* __restrict__ W_fc,
            const float* __restrict__ b_fc,
            float* __restrict__ out, int B)
{
    // hbuf[phase][warp][row][unit] : phase stride 1024B, row stride 128B
    __shared__ __align__(16) float hbuf[2][WARPS_PER_CTA][ROWS_PER_WARP][32];
    __shared__ __align__(16) float xsm[WARPS_PER_CTA][ROWS_PER_WARP][32];

    const int wl   = threadIdx.x >> 5;
    const int lane = threadIdx.x & 31;
    const int bA   = (blockIdx.x * WARPS_PER_CTA + wl) * ROWS_PER_WARP;
    const int bB   = bA + 1;
    if (bA >= B) return;

    // sigmoid(a)=rcp(1+ex2(-log2e*a)); tanh(a)=fma(-2, rcp(1+ex2(2*log2e*a)), 1)
    const float SG0 = -1.4426950408889634f;  // i
    const float SG1 = -1.4426950408889634f;  // f
    const float SG2 =  2.8853900817779268f;  // g (tanh)
    const float SG3 = -1.4426950408889634f;  // o

    // ---- weights, gate-major k-pairs (scales folded): 64 u64 = 128 regs ----
    u64 w0[16], w1[16], w2[16], w3[16];
#pragma unroll
    for (int q = 0; q < 16; q++) {
        const float* r0 = W_hh + (lane)      * 32 + 2 * q;
        const float* r1 = W_hh + (32 + lane) * 32 + 2 * q;
        const float* r2 = W_hh + (64 + lane) * 32 + 2 * q;
        const float* r3 = W_hh + (96 + lane) * 32 + 2 * q;
        w0[q] = pack2(SG0 * r0[0], SG0 * r0[1]);
        w1[q] = pack2(SG1 * r1[0], SG1 * r1[1]);
        w2[q] = pack2(SG2 * r2[0], SG2 * r2[1]);
        w3[q] = pack2(SG3 * r3[0], SG3 * r3[1]);
    }
    const float wih0 = SG0 * W_ih[lane],      bia0 = SG0 * (b_ih[lane]      + b_hh[lane]);
    const float wih1 = SG1 * W_ih[32 + lane], bia1 = SG1 * (b_ih[32 + lane] + b_hh[32 + lane]);
    const float wih2 = SG2 * W_ih[64 + lane], bia2 = SG2 * (b_ih[64 + lane] + b_hh[64 + lane]);
    const float wih3 = SG3 * W_ih[96 + lane], bia3 = SG3 * (b_ih[96 + lane] + b_hh[96 + lane]);

    float hA = 0.f, cA = 0.f, hB = 0.f, cB = 0.f;
    hbuf[0][wl][0][lane] = 0.0f;
    hbuf[0][wl][1][lane] = 0.0f;

    // base smem addr for this warp's phase-0 row-A h buffer; offsets:
    //   +1024 -> phase 1, +128 -> row B, +lane*4 -> write slot
    const u32 hb = smem_u32(&hbuf[0][wl][0][0]);
    const float* xspA = &xsm[wl][0][0];
    const float* xspB = &xsm[wl][1][0];
    const float* xbA  = x + (size_t)bA * TSTEPS;
    const float* xbB  = x + (size_t)bB * TSTEPS;

// one row-step: RD/WR are u32 smem byte addrs (phase/row pre-folded)
#define STEP(XV, RD, WR, HS, CS)                                               \
    {                                                                          \
        const float xv = (XV);                                                 \
        u64 a0 = 0ull, a1 = 0ull, a2 = 0ull, a3 = 0ull;                        \
        _Pragma("unroll")                                                      \
        for (int m = 0; m < 8; m++) {                                          \
            u64 pA_, pB_;                                                      \
            lds2((RD) + m * 16, pA_, pB_);                                     \
            a0 = fma2(w0[2 * m],     pA_, a0);                                 \
            a1 = fma2(w1[2 * m],     pA_, a1);                                 \
            a2 = fma2(w2[2 * m],     pA_, a2);                                 \
            a3 = fma2(w3[2 * m],     pA_, a3);                                 \
            a0 = fma2(w0[2 * m + 1], pB_, a0);                                 \
            a1 = fma2(w1[2 * m + 1], pB_, a1);                                 \
            a2 = fma2(w2[2 * m + 1], pB_, a2);                                 \
            a3 = fma2(w3[2 * m + 1], pB_, a3);                                 \
        }                                                                      \
        float l0, u0_, l1, u1_, l2, u2_, l3, u3_;                              \
        unpack2(a0, l0, u0_);                                                  \
        unpack2(a1, l1, u1_);                                                  \
        unpack2(a2, l2, u2_);                                                  \
        unpack2(a3, l3, u3_);                                                  \
        const float s0 = fmaf(xv, wih0, bia0) + (l0 + u0_);                    \
        const float s1 = fmaf(xv, wih1, bia1) + (l1 + u1_);                    \
        const float s2 = fmaf(xv, wih2, bia2) + (l2 + u2_);                    \
        const float s3 = fmaf(xv, wih3, bia3) + (l3 + u3_);                    \
        const float ig = rcpf(1.0f + ex2f(s0));                                \
        const float fg = rcpf(1.0f + ex2f(s1));                                \
        const float gg = fmaf(-2.0f, rcpf(1.0f + ex2f(s2)), 1.0f);             \
        const float og = rcpf(1.0f + ex2f(s3));                                \
        (CS) = fmaf(fg, (CS), ig * gg);                                        \
        (HS) = og * tanhf_((CS));                                              \
        asm volatile("st.shared.f32 [%0], %1;"                                 \
                     :: "r"((WR) + lane * 4), "f"(HS) : "memory");             \
        __syncwarp();                                                          \
    }

#pragma unroll 1
    for (int tc = 0; tc < TSTEPS; tc += 32) {
        xsm[wl][0][lane] = xbA[tc + lane];   // coalesced 128B per warp
        xsm[wl][1][lane] = xbB[tc + lane];
        __syncwarp();

#pragma unroll 1
        for (int tt = 0; tt < 32; tt += 2) {
            // phase 0 -> 1
            STEP(xspA[tt],     hb,        hb + 1024,        hA, cA)
            STEP(xspB[tt],     hb + 128,  hb + 1024 + 128,  hB, cB)
            // phase 1 -> 0
            STEP(xspA[tt + 1], hb + 1024,       hb,         hA, cA)
            STEP(xspB[tt + 1], hb + 1024 + 128, hb + 128,   hB, cB)
        }
    }
#undef STEP

    // ---- final head: out[b] = dot(h, W_fc) + b_fc ----
    const float wfc = W_fc[lane];
    float pA = hA * wfc, pB = hB * wfc;
#pragma unroll
    for (int off = 16; off; off >>= 1) {
        pA += __shfl_xor_sync(0xffffffffu, pA, off);
        pB += __shfl_xor_sync(0xffffffffu, pB, off);
    }
    if (lane == 0) {
        out[bA] = pA + b_fc[0];
        if (bB < B) out[bB] = pB + b_fc[0];
    }
}

extern "C" void kernel_launch(void* const* d_in, const int* in_sizes, int n_in,
                              void* d_out, int out_size)
{
    const float* x    = (const float*)d_in[0];
    const float* W_ih = (const float*)d_in[1];
    const float* W_hh = (const float*)d_in[2];
    const float* b_ih = (const float*)d_in[3];
    const float* b_hh = (const float*)d_in[4];
    const float* W_fc = (const float*)d_in[5];
    const float* b_fc = (const float*)d_in[6];
    float* out = (float*)d_out;

    int B = in_sizes[0] / TSTEPS;  // x is [B, 512, 1]
    int rows_per_cta = WARPS_PER_CTA * ROWS_PER_WARP;
    int blocks = (B + rows_per_cta - 1) / rows_per_cta;
    lstm_kernel<<<blocks, 32 * WARPS_PER_CTA>>>(x, W_ih, W_hh, b_ih, b_hh, W_fc, b_fc, out, B);
}